// round 1
// baseline (speedup 1.0000x reference)
#include <cuda_runtime.h>
#include <stdint.h>
#include <math.h>

#define BATCH 4
#define SEQ   2048
#define DIN   1024
#define DD    64
#define QT    32
#define KT    64

// ---------------------------------------------------------------------------
// Device scratch (no cudaMalloc allowed)
// ---------------------------------------------------------------------------
__device__ float g_Q[BATCH * SEQ * DD];
__device__ float g_K[BATCH * SEQ * DD];
__device__ float g_V[BATCH * SEQ * DD];

// ---------------------------------------------------------------------------
// Host-side replication of np.random.default_rng(0) mask-index generation
// (SeedSequence -> PCG64 XSL-RR -> Lemire bounded -> Floyd's choice -> shuffle)
// ---------------------------------------------------------------------------
struct u128h { uint64_t hi, lo; };

static inline uint64_t mulhi64_h(uint64_t a, uint64_t b) {
  uint64_t al = (uint32_t)a, ah = a >> 32, bl = (uint32_t)b, bh = b >> 32;
  uint64_t p0 = al * bl, p1 = al * bh, p2 = ah * bl, p3 = ah * bh;
  uint64_t mid = (p0 >> 32) + (uint32_t)p1 + (uint32_t)p2;
  return p3 + (p1 >> 32) + (p2 >> 32) + (mid >> 32);
}

struct PCG64H {
  u128h state, inc;
  int has_uint32;
  uint32_t uinteger;
};

static inline void pcg_step_h(PCG64H* p) {
  // state = state * MULT + inc (mod 2^128)
  const uint64_t mhi = 2549297995355413924ULL, mlo = 4865540595714422341ULL;
  u128h s = p->state, r;
  r.lo = s.lo * mlo;
  r.hi = mulhi64_h(s.lo, mlo) + s.lo * mhi + s.hi * mlo;
  // + inc
  uint64_t lo = r.lo + p->inc.lo;
  r.hi += p->inc.hi + (lo < r.lo);
  r.lo = lo;
  p->state = r;
}

static inline uint64_t rotr64_h(uint64_t v, unsigned r) {
  r &= 63u;
  return r ? ((v >> r) | (v << (64 - r))) : v;
}

static inline uint64_t pcg_next64_h(PCG64H* p) {
  pcg_step_h(p);
  return rotr64_h(p->state.hi ^ p->state.lo, (unsigned)(p->state.hi >> 58));
}

static inline uint32_t pcg_next32_h(PCG64H* p) {
  if (p->has_uint32) { p->has_uint32 = 0; return p->uinteger; }
  uint64_t n = pcg_next64_h(p);
  p->has_uint32 = 1;
  p->uinteger = (uint32_t)(n >> 32);
  return (uint32_t)n;
}

// numpy SeedSequence(0).generate_state(4, uint64)
static void seedseq0_state_h(uint64_t out[4]) {
  const uint32_t INIT_A = 0x43b0d7e5u, MULT_A = 0x931e8875u;
  const uint32_t INIT_B = 0x8b51f9ddu, MULT_B = 0x58f38dedu;
  const uint32_t MIX_L = 0xca01f9ddu, MIX_R = 0x4973f715u;
  uint32_t pool[4];
  uint32_t hc = INIT_A;
  // hashmix with evolving constant
  for (int i = 0; i < 4; i++) {
    uint32_t v = 0u;  // entropy[0] = 0, then zero-fill
    v ^= hc; hc *= MULT_A; v *= hc; v ^= v >> 16;
    pool[i] = v;
  }
  for (int s = 0; s < 4; s++) {
    for (int d = 0; d < 4; d++) {
      if (s == d) continue;
      uint32_t v = pool[s];
      v ^= hc; hc *= MULT_A; v *= hc; v ^= v >> 16;
      uint32_t r = (pool[d] * MIX_L) ^ (v * MIX_R);
      r ^= r >> 16;
      pool[d] = r;
    }
  }
  uint32_t hcb = INIT_B;
  uint32_t st[8];
  for (int i = 0; i < 8; i++) {
    uint32_t dv = pool[i & 3];
    dv ^= hcb; hcb *= MULT_B; dv *= hcb; dv ^= dv >> 16;
    st[i] = dv;
  }
  for (int k2 = 0; k2 < 4; k2++)
    out[k2] = (uint64_t)st[2 * k2] | ((uint64_t)st[2 * k2 + 1] << 32);
}

// Lemire bounded [0, rng] inclusive, 32-bit path (rng < 2^32-1)
static inline uint64_t lemire32_h(PCG64H* p, uint32_t rng) {
  if (rng == 0) return 0;
  const uint32_t rng_excl = rng + 1;
  uint64_t m = (uint64_t)pcg_next32_h(p) * (uint64_t)rng_excl;
  uint32_t leftover = (uint32_t)m;
  if (leftover < rng_excl) {
    const uint32_t threshold = (uint32_t)(0xFFFFFFFFu - rng) % rng_excl;
    while (leftover < threshold) {
      m = (uint64_t)pcg_next32_h(p) * (uint64_t)rng_excl;
      leftover = (uint32_t)m;
    }
  }
  return m >> 32;
}

// Generator.choice(2048, 3, replace=False) : Floyd's algorithm + shuffle
static void choice3_2048_h(PCG64H* p, int64_t idx[3]) {
  const int size = 3, pop = 2048;
  const uint64_t mask = 3;  // _gen_mask(uint64(1.2*3)=3) -> 3
  uint64_t hset[4] = {~0ull, ~0ull, ~0ull, ~0ull};
  for (int j = pop - size; j < pop; j++) {
    uint64_t val = lemire32_h(p, (uint32_t)j);
    uint64_t loc = val & mask;
    while (hset[loc] != ~0ull && hset[loc] != val) loc = (loc + 1) & mask;
    if (hset[loc] == ~0ull) {
      hset[loc] = val;
      idx[j - pop + size] = (int64_t)val;
    } else {
      loc = (uint64_t)j & mask;
      while (hset[loc] != ~0ull) loc = (loc + 1) & mask;
      hset[loc] = (uint64_t)j;
      idx[j - pop + size] = (int64_t)j;
    }
  }
  // Generator.shuffle(idx): Fisher-Yates with Lemire bounded draws
  for (int i = size - 1; i >= 1; i--) {
    uint64_t jj = lemire32_h(p, (uint32_t)i);
    if ((int)jj != i) {
      int64_t t = idx[i]; idx[i] = idx[(int)jj]; idx[(int)jj] = t;
    }
  }
}

static void compute_mask_pairs_h(int gr[3], int gc[3]) {
  uint64_t sd[4];
  seedseq0_state_h(sd);
  PCG64H rng;
  // srandom: state=0; inc=(initseq<<1)|1; step; state+=initstate; step
  rng.inc.hi = (sd[2] << 1) | (sd[3] >> 63);
  rng.inc.lo = (sd[3] << 1) | 1ull;
  rng.state.hi = 0; rng.state.lo = 0;
  pcg_step_h(&rng);
  uint64_t lo = rng.state.lo + sd[1];
  rng.state.hi += sd[0] + (lo < rng.state.lo);
  rng.state.lo = lo;
  pcg_step_h(&rng);
  rng.has_uint32 = 0; rng.uinteger = 0;

  int64_t rows[3], cols[3];
  choice3_2048_h(&rng, rows);
  choice3_2048_h(&rng, cols);
  for (int i = 0; i < 3; i++) { gr[i] = (int)rows[i]; gc[i] = (int)cols[i]; }
}

// ---------------------------------------------------------------------------
// Projection GEMM: out[m,n] = sum_k A[m,k]*W[k,n] + b[n]
// M = 8192, K = 1024, N = 64.  Tile: 128 rows x 64 cols, k-chunk 32.
// 256 threads, micro-tile 8 rows (stride 16) x 4 cols.
// ---------------------------------------------------------------------------
__global__ __launch_bounds__(256) void proj_kernel(
    const float* __restrict__ in_q, const float* __restrict__ in_k,
    const float* __restrict__ in_v,
    const float* __restrict__ Wq, const float* __restrict__ bq,
    const float* __restrict__ Wk, const float* __restrict__ bk,
    const float* __restrict__ Wv, const float* __restrict__ bv) {
  const float* A; const float* W; const float* bias; float* out;
  int z = blockIdx.z;
  if (z == 0)      { A = in_q; W = Wq; bias = bq; out = g_Q; }
  else if (z == 1) { A = in_k; W = Wk; bias = bk; out = g_K; }
  else             { A = in_v; W = Wv; bias = bv; out = g_V; }

  __shared__ float As[128][36];  // +4 pad
  __shared__ float Ws[32][64];

  const int t = threadIdx.x;
  const int m0 = blockIdx.x * 128;
  const int tr = t >> 4;           // 0..15: rows tr, tr+16, ..., tr+112
  const int tc = (t & 15) * 4;     // cols tc..tc+3

  float acc[8][4];
#pragma unroll
  for (int i = 0; i < 8; i++)
#pragma unroll
    for (int j = 0; j < 4; j++) acc[i][j] = 0.f;

  const int f4row = t >> 3;        // 0..31
  const int f4col = t & 7;         // 0..7

  for (int k0 = 0; k0 < DIN; k0 += 32) {
    // A tile 128x32
#pragma unroll
    for (int rr = 0; rr < 4; rr++) {
      int row = f4row + rr * 32;
      float4 vv = *(const float4*)&A[(size_t)(m0 + row) * DIN + k0 + f4col * 4];
      *(float4*)&As[row][f4col * 4] = vv;
    }
    // W tile 32x64
#pragma unroll
    for (int ww = 0; ww < 2; ww++) {
      int idx = t + ww * 256;
      int row = idx >> 4;
      int c4 = idx & 15;
      float4 vv = *(const float4*)&W[(size_t)(k0 + row) * DD + c4 * 4];
      *(float4*)&Ws[row][c4 * 4] = vv;
    }
    __syncthreads();
#pragma unroll
    for (int kk = 0; kk < 32; kk++) {
      float4 wv = *(const float4*)&Ws[kk][tc];
      float a[8];
#pragma unroll
      for (int i = 0; i < 8; i++) a[i] = As[tr + 16 * i][kk];
#pragma unroll
      for (int i = 0; i < 8; i++) {
        acc[i][0] = fmaf(a[i], wv.x, acc[i][0]);
        acc[i][1] = fmaf(a[i], wv.y, acc[i][1]);
        acc[i][2] = fmaf(a[i], wv.z, acc[i][2]);
        acc[i][3] = fmaf(a[i], wv.w, acc[i][3]);
      }
    }
    __syncthreads();
  }

  float4 bb = *(const float4*)&bias[tc];
#pragma unroll
  for (int i = 0; i < 8; i++) {
    float4 o = make_float4(acc[i][0] + bb.x, acc[i][1] + bb.y,
                           acc[i][2] + bb.z, acc[i][3] + bb.w);
    *(float4*)&out[(size_t)(m0 + tr + 16 * i) * DD + tc] = o;
  }
}

// ---------------------------------------------------------------------------
// Flash attention, fp32, causal + 3 global (row,col) unmask pairs.
// Grid: BATCH * (SEQ/QT) = 256 blocks, 256 threads.
// Thread (r = t>>3, sub = t&7): row r of q-tile; owns output dims sub*8..+8;
// score columns j = sub + 8*jj (conflict-free K reads with +4 row pad).
// ---------------------------------------------------------------------------
__global__ __launch_bounds__(256) void attn_kernel(
    float* __restrict__ out,
    int gr0, int gc0, int gr1, int gc1, int gr2, int gc2) {
  const int bid = blockIdx.x;
  const int b = bid >> 6;
  const int qt = bid & 63;
  const int qr0 = qt * QT;
  const float* __restrict__ Qb = g_Q + (size_t)b * SEQ * DD;
  const float* __restrict__ Kb = g_K + (size_t)b * SEQ * DD;
  const float* __restrict__ Vb = g_V + (size_t)b * SEQ * DD;

  __shared__ float Qs[QT][DD + 4];
  __shared__ float KPs[KT][DD + 4];  // K tile; reused as P (rows 0..QT-1)
  __shared__ float Vs[KT][DD + 4];

  const int t = threadIdx.x;
  const int r = t >> 3;
  const int sub = t & 7;
  const int d0 = sub * 8;
  const int rg = qr0 + r;
  const float scale = 0.125f;  // 1/sqrt(64)

  // load Q tile
  for (int i = t; i < QT * 16; i += 256) {
    int row = i >> 4, c4 = i & 15;
    *(float4*)&Qs[row][c4 * 4] =
        *(const float4*)&Qb[(size_t)(qr0 + row) * DD + c4 * 4];
  }

  float m = -INFINITY, l = 0.f;
  float acc[8];
#pragma unroll
  for (int i = 0; i < 8; i++) acc[i] = 0.f;

  const int ktmax = (qr0 + QT - 1) >> 6;

  for (int kt = 0; kt <= ktmax; kt++) {
    const int j0 = kt * KT;
    __syncthreads();  // previous iteration done with KPs/Vs (and Q load done)
    for (int i = t; i < KT * 16; i += 256) {
      int row = i >> 4, c4 = i & 15;
      *(float4*)&KPs[row][c4 * 4] =
          *(const float4*)&Kb[(size_t)(j0 + row) * DD + c4 * 4];
      *(float4*)&Vs[row][c4 * 4] =
          *(const float4*)&Vb[(size_t)(j0 + row) * DD + c4 * 4];
    }
    __syncthreads();

    // scores: 8 per thread, columns sub + 8*jj
    float s[8];
#pragma unroll
    for (int jj = 0; jj < 8; jj++) s[jj] = 0.f;
#pragma unroll
    for (int d = 0; d < DD; d += 4) {
      float4 qv = *(const float4*)&Qs[r][d];
#pragma unroll
      for (int jj = 0; jj < 8; jj++) {
        float4 kv = *(const float4*)&KPs[sub + jj * 8][d];
        s[jj] = fmaf(qv.x, kv.x, s[jj]);
        s[jj] = fmaf(qv.y, kv.y, s[jj]);
        s[jj] = fmaf(qv.z, kv.z, s[jj]);
        s[jj] = fmaf(qv.w, kv.w, s[jj]);
      }
    }
    float smax = -INFINITY;
#pragma unroll
    for (int jj = 0; jj < 8; jj++) {
      int jg = j0 + sub + jj * 8;
      s[jj] = (jg <= rg) ? s[jj] * scale : -INFINITY;
      smax = fmaxf(smax, s[jj]);
    }
    smax = fmaxf(smax, __shfl_xor_sync(0xffffffffu, smax, 1));
    smax = fmaxf(smax, __shfl_xor_sync(0xffffffffu, smax, 2));
    smax = fmaxf(smax, __shfl_xor_sync(0xffffffffu, smax, 4));
    const float mnew = fmaxf(m, smax);
    const float corr = expf(m - mnew);

    float p[8];
    float psum = 0.f;
#pragma unroll
    for (int jj = 0; jj < 8; jj++) {
      p[jj] = (s[jj] == -INFINITY) ? 0.f : expf(s[jj] - mnew);
      psum += p[jj];
    }
    psum += __shfl_xor_sync(0xffffffffu, psum, 1);
    psum += __shfl_xor_sync(0xffffffffu, psum, 2);
    psum += __shfl_xor_sync(0xffffffffu, psum, 4);
    l = l * corr + psum;
    m = mnew;
#pragma unroll
    for (int i = 0; i < 8; i++) acc[i] *= corr;

    __syncthreads();  // everyone done reading K
#pragma unroll
    for (int jj = 0; jj < 8; jj++) KPs[r][sub + jj * 8] = p[jj];
    __syncthreads();

    // O += P @ V  (thread: row r, dims d0..d0+7)
#pragma unroll
    for (int j = 0; j < KT; j += 4) {
      float4 pv = *(const float4*)&KPs[r][j];
      float pvals[4] = {pv.x, pv.y, pv.z, pv.w};
#pragma unroll
      for (int u = 0; u < 4; u++) {
        float pj = pvals[u];
        float4 v0 = *(const float4*)&Vs[j + u][d0];
        float4 v1 = *(const float4*)&Vs[j + u][d0 + 4];
        acc[0] = fmaf(pj, v0.x, acc[0]);
        acc[1] = fmaf(pj, v0.y, acc[1]);
        acc[2] = fmaf(pj, v0.z, acc[2]);
        acc[3] = fmaf(pj, v0.w, acc[3]);
        acc[4] = fmaf(pj, v1.x, acc[4]);
        acc[5] = fmaf(pj, v1.y, acc[5]);
        acc[6] = fmaf(pj, v1.z, acc[6]);
        acc[7] = fmaf(pj, v1.w, acc[7]);
      }
    }
  }

  // global-token corrections (unmasked (gr,gc) with gc > gr)
  const int grs[3] = {gr0, gr1, gr2};
  const int gcs[3] = {gc0, gc1, gc2};
#pragma unroll
  for (int g = 0; g < 3; g++) {
    int grr = grs[g], gcc = gcs[g];
    if (grr >= qr0 && grr < qr0 + QT && gcc > grr) {  // block-uniform branch
      bool act = (rg == grr);
      float part = 0.f;
#pragma unroll
      for (int dd = 0; dd < 8; dd++)
        part += Qs[r][d0 + dd] * Kb[(size_t)gcc * DD + d0 + dd];
      part += __shfl_xor_sync(0xffffffffu, part, 1);
      part += __shfl_xor_sync(0xffffffffu, part, 2);
      part += __shfl_xor_sync(0xffffffffu, part, 4);
      float sg = part * scale;
      float mnew = fmaxf(m, sg);
      float corr = expf(m - mnew);
      float pg = expf(sg - mnew);
      if (act) {
        l = l * corr + pg;
        m = mnew;
#pragma unroll
        for (int i = 0; i < 8; i++)
          acc[i] = fmaf(pg, Vb[(size_t)gcc * DD + d0 + i], acc[i] * corr);
      }
    }
  }

  const float inv = 1.f / l;
  float4 o0 = make_float4(acc[0] * inv, acc[1] * inv, acc[2] * inv, acc[3] * inv);
  float4 o1 = make_float4(acc[4] * inv, acc[5] * inv, acc[6] * inv, acc[7] * inv);
  float* orow = &out[((size_t)b * SEQ + rg) * DD + d0];
  *(float4*)&orow[0] = o0;
  *(float4*)&orow[4] = o1;
}

// ---------------------------------------------------------------------------
extern "C" void kernel_launch(void* const* d_in, const int* in_sizes, int n_in,
                              void* d_out, int out_size) {
  const float* q  = (const float*)d_in[0];
  const float* k  = (const float*)d_in[1];
  const float* v  = (const float*)d_in[2];
  const float* Wq = (const float*)d_in[3];
  const float* bq = (const float*)d_in[4];
  const float* Wk = (const float*)d_in[5];
  const float* bk = (const float*)d_in[6];
  const float* Wv = (const float*)d_in[7];
  const float* bv = (const float*)d_in[8];
  float* out = (float*)d_out;

  int gr[3], gc[3];
  compute_mask_pairs_h(gr, gc);

  dim3 pg(64, 1, 3);
  proj_kernel<<<pg, 256>>>(q, k, v, Wq, bq, Wk, bk, Wv, bv);
  attn_kernel<<<BATCH * (SEQ / QT), 256>>>(out, gr[0], gc[0], gr[1], gc[1],
                                           gr[2], gc[2]);
}

// round 2
// speedup vs baseline: 1.6037x; 1.6037x over previous
#include <cuda_runtime.h>
#include <stdint.h>
#include <math.h>

#define BATCH 4
#define SEQ   2048
#define DIN   1024
#define DD    64
#define QT    32
#define KT    64
#define S_SPLIT 3
#define NEGF  -1e30f

// ---------------------------------------------------------------------------
// Device scratch (no cudaMalloc allowed)
// ---------------------------------------------------------------------------
__device__ float g_Q[BATCH * SEQ * DD];
__device__ float g_K[BATCH * SEQ * DD];
__device__ float g_V[BATCH * SEQ * DD];
__device__ float g_pacc[S_SPLIT * BATCH * SEQ * DD];
__device__ float g_pm[S_SPLIT * BATCH * SEQ];
__device__ float g_pl[S_SPLIT * BATCH * SEQ];

// ---------------------------------------------------------------------------
// Host-side replication of np.random.default_rng(0) mask-index generation
// (SeedSequence -> PCG64 XSL-RR -> Lemire bounded -> Floyd's choice -> shuffle)
// ---------------------------------------------------------------------------
struct u128h { uint64_t hi, lo; };

static inline uint64_t mulhi64_h(uint64_t a, uint64_t b) {
  uint64_t al = (uint32_t)a, ah = a >> 32, bl = (uint32_t)b, bh = b >> 32;
  uint64_t p0 = al * bl, p1 = al * bh, p2 = ah * bl, p3 = ah * bh;
  uint64_t mid = (p0 >> 32) + (uint32_t)p1 + (uint32_t)p2;
  return p3 + (p1 >> 32) + (p2 >> 32) + (mid >> 32);
}

struct PCG64H {
  u128h state, inc;
  int has_uint32;
  uint32_t uinteger;
};

static inline void pcg_step_h(PCG64H* p) {
  const uint64_t mhi = 2549297995355413924ULL, mlo = 4865540595714422341ULL;
  u128h s = p->state, r;
  r.lo = s.lo * mlo;
  r.hi = mulhi64_h(s.lo, mlo) + s.lo * mhi + s.hi * mlo;
  uint64_t lo = r.lo + p->inc.lo;
  r.hi += p->inc.hi + (lo < r.lo);
  r.lo = lo;
  p->state = r;
}

static inline uint64_t rotr64_h(uint64_t v, unsigned r) {
  r &= 63u;
  return r ? ((v >> r) | (v << (64 - r))) : v;
}

static inline uint64_t pcg_next64_h(PCG64H* p) {
  pcg_step_h(p);
  return rotr64_h(p->state.hi ^ p->state.lo, (unsigned)(p->state.hi >> 58));
}

static inline uint32_t pcg_next32_h(PCG64H* p) {
  if (p->has_uint32) { p->has_uint32 = 0; return p->uinteger; }
  uint64_t n = pcg_next64_h(p);
  p->has_uint32 = 1;
  p->uinteger = (uint32_t)(n >> 32);
  return (uint32_t)n;
}

static void seedseq0_state_h(uint64_t out[4]) {
  const uint32_t INIT_A = 0x43b0d7e5u, MULT_A = 0x931e8875u;
  const uint32_t INIT_B = 0x8b51f9ddu, MULT_B = 0x58f38dedu;
  const uint32_t MIX_L = 0xca01f9ddu, MIX_R = 0x4973f715u;
  uint32_t pool[4];
  uint32_t hc = INIT_A;
  for (int i = 0; i < 4; i++) {
    uint32_t v = 0u;
    v ^= hc; hc *= MULT_A; v *= hc; v ^= v >> 16;
    pool[i] = v;
  }
  for (int s = 0; s < 4; s++) {
    for (int d = 0; d < 4; d++) {
      if (s == d) continue;
      uint32_t v = pool[s];
      v ^= hc; hc *= MULT_A; v *= hc; v ^= v >> 16;
      uint32_t r = (pool[d] * MIX_L) ^ (v * MIX_R);
      r ^= r >> 16;
      pool[d] = r;
    }
  }
  uint32_t hcb = INIT_B;
  uint32_t st[8];
  for (int i = 0; i < 8; i++) {
    uint32_t dv = pool[i & 3];
    dv ^= hcb; hcb *= MULT_B; dv *= hcb; dv ^= dv >> 16;
    st[i] = dv;
  }
  for (int k2 = 0; k2 < 4; k2++)
    out[k2] = (uint64_t)st[2 * k2] | ((uint64_t)st[2 * k2 + 1] << 32);
}

static inline uint64_t lemire32_h(PCG64H* p, uint32_t rng) {
  if (rng == 0) return 0;
  const uint32_t rng_excl = rng + 1;
  uint64_t m = (uint64_t)pcg_next32_h(p) * (uint64_t)rng_excl;
  uint32_t leftover = (uint32_t)m;
  if (leftover < rng_excl) {
    const uint32_t threshold = (uint32_t)(0xFFFFFFFFu - rng) % rng_excl;
    while (leftover < threshold) {
      m = (uint64_t)pcg_next32_h(p) * (uint64_t)rng_excl;
      leftover = (uint32_t)m;
    }
  }
  return m >> 32;
}

static void choice3_2048_h(PCG64H* p, int64_t idx[3]) {
  const int size = 3, pop = 2048;
  const uint64_t mask = 3;
  uint64_t hset[4] = {~0ull, ~0ull, ~0ull, ~0ull};
  for (int j = pop - size; j < pop; j++) {
    uint64_t val = lemire32_h(p, (uint32_t)j);
    uint64_t loc = val & mask;
    while (hset[loc] != ~0ull && hset[loc] != val) loc = (loc + 1) & mask;
    if (hset[loc] == ~0ull) {
      hset[loc] = val;
      idx[j - pop + size] = (int64_t)val;
    } else {
      loc = (uint64_t)j & mask;
      while (hset[loc] != ~0ull) loc = (loc + 1) & mask;
      hset[loc] = (uint64_t)j;
      idx[j - pop + size] = (int64_t)j;
    }
  }
  for (int i = size - 1; i >= 1; i--) {
    uint64_t jj = lemire32_h(p, (uint32_t)i);
    if ((int)jj != i) {
      int64_t t = idx[i]; idx[i] = idx[(int)jj]; idx[(int)jj] = t;
    }
  }
}

static void compute_mask_pairs_h(int gr[3], int gc[3]) {
  uint64_t sd[4];
  seedseq0_state_h(sd);
  PCG64H rng;
  rng.inc.hi = (sd[2] << 1) | (sd[3] >> 63);
  rng.inc.lo = (sd[3] << 1) | 1ull;
  rng.state.hi = 0; rng.state.lo = 0;
  pcg_step_h(&rng);
  uint64_t lo = rng.state.lo + sd[1];
  rng.state.hi += sd[0] + (lo < rng.state.lo);
  rng.state.lo = lo;
  pcg_step_h(&rng);
  rng.has_uint32 = 0; rng.uinteger = 0;

  int64_t rows[3], cols[3];
  choice3_2048_h(&rng, rows);
  choice3_2048_h(&rng, cols);
  for (int i = 0; i < 3; i++) { gr[i] = (int)rows[i]; gc[i] = (int)cols[i]; }
}

// ---------------------------------------------------------------------------
// Projection GEMM (unchanged from R1 — already at fp32 FMA wall)
// ---------------------------------------------------------------------------
__global__ __launch_bounds__(256) void proj_kernel(
    const float* __restrict__ in_q, const float* __restrict__ in_k,
    const float* __restrict__ in_v,
    const float* __restrict__ Wq, const float* __restrict__ bq,
    const float* __restrict__ Wk, const float* __restrict__ bk,
    const float* __restrict__ Wv, const float* __restrict__ bv) {
  const float* A; const float* W; const float* bias; float* out;
  int z = blockIdx.z;
  if (z == 0)      { A = in_q; W = Wq; bias = bq; out = g_Q; }
  else if (z == 1) { A = in_k; W = Wk; bias = bk; out = g_K; }
  else             { A = in_v; W = Wv; bias = bv; out = g_V; }

  __shared__ float As[128][36];
  __shared__ float Ws[32][64];

  const int t = threadIdx.x;
  const int m0 = blockIdx.x * 128;
  const int tr = t >> 4;
  const int tc = (t & 15) * 4;

  float acc[8][4];
#pragma unroll
  for (int i = 0; i < 8; i++)
#pragma unroll
    for (int j = 0; j < 4; j++) acc[i][j] = 0.f;

  const int f4row = t >> 3;
  const int f4col = t & 7;

  for (int k0 = 0; k0 < DIN; k0 += 32) {
#pragma unroll
    for (int rr = 0; rr < 4; rr++) {
      int row = f4row + rr * 32;
      float4 vv = *(const float4*)&A[(size_t)(m0 + row) * DIN + k0 + f4col * 4];
      *(float4*)&As[row][f4col * 4] = vv;
    }
#pragma unroll
    for (int ww = 0; ww < 2; ww++) {
      int idx = t + ww * 256;
      int row = idx >> 4;
      int c4 = idx & 15;
      float4 vv = *(const float4*)&W[(size_t)(k0 + row) * DD + c4 * 4];
      *(float4*)&Ws[row][c4 * 4] = vv;
    }
    __syncthreads();
#pragma unroll
    for (int kk = 0; kk < 32; kk++) {
      float4 wv = *(const float4*)&Ws[kk][tc];
      float a[8];
#pragma unroll
      for (int i = 0; i < 8; i++) a[i] = As[tr + 16 * i][kk];
#pragma unroll
      for (int i = 0; i < 8; i++) {
        acc[i][0] = fmaf(a[i], wv.x, acc[i][0]);
        acc[i][1] = fmaf(a[i], wv.y, acc[i][1]);
        acc[i][2] = fmaf(a[i], wv.z, acc[i][2]);
        acc[i][3] = fmaf(a[i], wv.w, acc[i][3]);
      }
    }
    __syncthreads();
  }

  float4 bb = *(const float4*)&bias[tc];
#pragma unroll
  for (int i = 0; i < 8; i++) {
    float4 o = make_float4(acc[i][0] + bb.x, acc[i][1] + bb.y,
                           acc[i][2] + bb.z, acc[i][3] + bb.w);
    *(float4*)&out[(size_t)(m0 + tr + 16 * i) * DD + tc] = o;
  }
}

// ---------------------------------------------------------------------------
// Flash attention, split-K x3, fp32. Causal masking only; global-token
// corrections are applied in combine_kernel.
// Grid: S_SPLIT * BATCH * (SEQ/QT) = 768 blocks, 256 threads.
// Thread (r = t>>3, sub = t&7): q-row r; score cols sub + 8*jj;
// output dims: two slices {sub*4..+3} and {32+sub*4..+3} (conflict-free V).
// ---------------------------------------------------------------------------
__global__ __launch_bounds__(256) void attn_split_kernel() {
  const int bid = blockIdx.x;
  const int s = bid >> 8;            // 0..2
  const int rest = bid & 255;
  const int b = rest >> 6;
  const int qt = rest & 63;
  const int qr0 = qt * QT;
  const int T = (qt >> 1) + 1;       // number of 64-key tiles
  const int t0 = (s * T) / S_SPLIT;
  const int t1 = ((s + 1) * T) / S_SPLIT;

  const int t = threadIdx.x;
  const int r = t >> 3;
  const int sub = t & 7;
  const int rg = qr0 + r;
  const int d0a = sub * 4;
  const int d0b = 32 + sub * 4;

  const size_t prow = ((size_t)s * BATCH + b) * SEQ + qr0 + r;
  float* paccRow = g_pacc + prow * DD;

  if (t0 == t1) {  // empty split (uniform across block)
    if (sub == 0) { g_pm[prow] = NEGF; g_pl[prow] = 0.f; }
    *(float4*)&paccRow[d0a] = make_float4(0.f, 0.f, 0.f, 0.f);
    *(float4*)&paccRow[d0b] = make_float4(0.f, 0.f, 0.f, 0.f);
    return;
  }

  const float* __restrict__ Qb = g_Q + (size_t)b * SEQ * DD;
  const float* __restrict__ Kb = g_K + (size_t)b * SEQ * DD;
  const float* __restrict__ Vb = g_V + (size_t)b * SEQ * DD;

  __shared__ float Qs[QT][DD + 4];
  __shared__ float KPs[KT][DD + 4];  // K tile; reused as P
  __shared__ float Vs[KT][DD + 4];

  const float scale = 0.125f;

  // load Q tile
  for (int i = t; i < QT * 16; i += 256) {
    int row = i >> 4, c4 = i & 15;
    *(float4*)&Qs[row][c4 * 4] =
        *(const float4*)&Qb[(size_t)(qr0 + row) * DD + c4 * 4];
  }

  float m = NEGF, l = 0.f;
  float acc[8];
#pragma unroll
  for (int i = 0; i < 8; i++) acc[i] = 0.f;

  for (int kt = t0; kt < t1; kt++) {
    const int j0 = kt * KT;
    const bool masked = (kt == T - 1);
    __syncthreads();
    for (int i = t; i < KT * 16; i += 256) {
      int row = i >> 4, c4 = i & 15;
      *(float4*)&KPs[row][c4 * 4] =
          *(const float4*)&Kb[(size_t)(j0 + row) * DD + c4 * 4];
      *(float4*)&Vs[row][c4 * 4] =
          *(const float4*)&Vb[(size_t)(j0 + row) * DD + c4 * 4];
    }
    __syncthreads();

    float sc[8];
#pragma unroll
    for (int jj = 0; jj < 8; jj++) sc[jj] = 0.f;
#pragma unroll
    for (int d = 0; d < DD; d += 4) {
      float4 qv = *(const float4*)&Qs[r][d];
#pragma unroll
      for (int jj = 0; jj < 8; jj++) {
        float4 kv = *(const float4*)&KPs[sub + jj * 8][d];
        sc[jj] = fmaf(qv.x, kv.x, sc[jj]);
        sc[jj] = fmaf(qv.y, kv.y, sc[jj]);
        sc[jj] = fmaf(qv.z, kv.z, sc[jj]);
        sc[jj] = fmaf(qv.w, kv.w, sc[jj]);
      }
    }
    float smax = NEGF;
    if (masked) {
#pragma unroll
      for (int jj = 0; jj < 8; jj++) {
        int jg = j0 + sub + jj * 8;
        sc[jj] = (jg <= rg) ? sc[jj] * scale : NEGF;
        smax = fmaxf(smax, sc[jj]);
      }
    } else {
#pragma unroll
      for (int jj = 0; jj < 8; jj++) {
        sc[jj] *= scale;
        smax = fmaxf(smax, sc[jj]);
      }
    }
    smax = fmaxf(smax, __shfl_xor_sync(0xffffffffu, smax, 1));
    smax = fmaxf(smax, __shfl_xor_sync(0xffffffffu, smax, 2));
    smax = fmaxf(smax, __shfl_xor_sync(0xffffffffu, smax, 4));
    const float mnew = fmaxf(m, smax);
    const float corr = __expf(m - mnew);  // m=NEGF underflows to 0

    float p[8];
    float psum = 0.f;
#pragma unroll
    for (int jj = 0; jj < 8; jj++) {
      p[jj] = __expf(sc[jj] - mnew);  // NEGF - mnew underflows to 0
      psum += p[jj];
    }
    psum += __shfl_xor_sync(0xffffffffu, psum, 1);
    psum += __shfl_xor_sync(0xffffffffu, psum, 2);
    psum += __shfl_xor_sync(0xffffffffu, psum, 4);
    l = l * corr + psum;
    m = mnew;
#pragma unroll
    for (int i = 0; i < 8; i++) acc[i] *= corr;

    __syncthreads();
#pragma unroll
    for (int jj = 0; jj < 8; jj++) KPs[r][sub + jj * 8] = p[jj];
    __syncthreads();

    // O += P @ V : thread row r, dims {d0a..+3, d0b..+3}
#pragma unroll
    for (int j = 0; j < KT; j += 4) {
      float4 pv = *(const float4*)&KPs[r][j];
      float pvals[4] = {pv.x, pv.y, pv.z, pv.w};
#pragma unroll
      for (int u = 0; u < 4; u++) {
        float pj = pvals[u];
        float4 va = *(const float4*)&Vs[j + u][d0a];
        float4 vb = *(const float4*)&Vs[j + u][d0b];
        acc[0] = fmaf(pj, va.x, acc[0]);
        acc[1] = fmaf(pj, va.y, acc[1]);
        acc[2] = fmaf(pj, va.z, acc[2]);
        acc[3] = fmaf(pj, va.w, acc[3]);
        acc[4] = fmaf(pj, vb.x, acc[4]);
        acc[5] = fmaf(pj, vb.y, acc[5]);
        acc[6] = fmaf(pj, vb.z, acc[6]);
        acc[7] = fmaf(pj, vb.w, acc[7]);
      }
    }
  }

  if (sub == 0) { g_pm[prow] = m; g_pl[prow] = l; }
  *(float4*)&paccRow[d0a] = make_float4(acc[0], acc[1], acc[2], acc[3]);
  *(float4*)&paccRow[d0b] = make_float4(acc[4], acc[5], acc[6], acc[7]);
}

// ---------------------------------------------------------------------------
// Combine splits + apply global-token corrections + normalize + write out.
// Grid: BATCH * (SEQ/32) = 256 blocks, 256 threads (r = t>>3, sub = t&7).
// ---------------------------------------------------------------------------
__global__ __launch_bounds__(256) void combine_kernel(
    float* __restrict__ out,
    int gr0, int gc0, int gr1, int gc1, int gr2, int gc2) {
  const int bid = blockIdx.x;
  const int b = bid >> 6;
  const int rt = bid & 63;
  const int t = threadIdx.x;
  const int r = t >> 3;
  const int sub = t & 7;
  const int row = rt * 32 + r;
  const int d0a = sub * 4;
  const int d0b = 32 + sub * 4;
  const size_t browoff = (size_t)b * SEQ + row;

  float ms[S_SPLIT], ls[S_SPLIT];
  float M = NEGF;
#pragma unroll
  for (int s = 0; s < S_SPLIT; s++) {
    size_t prow = ((size_t)s * BATCH + b) * SEQ + row;
    ms[s] = g_pm[prow];
    ls[s] = g_pl[prow];
    M = fmaxf(M, ms[s]);
  }
  float L = 0.f;
  float4 Aa = make_float4(0.f, 0.f, 0.f, 0.f);
  float4 Ab = make_float4(0.f, 0.f, 0.f, 0.f);
#pragma unroll
  for (int s = 0; s < S_SPLIT; s++) {
    size_t prow = ((size_t)s * BATCH + b) * SEQ + row;
    float w = __expf(ms[s] - M);
    L += ls[s] * w;
    const float* pr = g_pacc + prow * DD;
    float4 pa = *(const float4*)&pr[d0a];
    float4 pb = *(const float4*)&pr[d0b];
    Aa.x += w * pa.x; Aa.y += w * pa.y; Aa.z += w * pa.z; Aa.w += w * pa.w;
    Ab.x += w * pb.x; Ab.y += w * pb.y; Ab.z += w * pb.z; Ab.w += w * pb.w;
  }

  // global-token corrections (only (gr,gc) with gc > gr change anything)
  const int grs[3] = {gr0, gr1, gr2};
  const int gcs[3] = {gc0, gc1, gc2};
  const float* __restrict__ Qrow = g_Q + browoff * DD;
#pragma unroll
  for (int g = 0; g < 3; g++) {
    int grr = grs[g], gcc = gcs[g];
    if (row == grr && gcc > grr) {  // uniform across the 8 sub lanes
      const float* Kg = g_K + ((size_t)b * SEQ + gcc) * DD;
      const float* Vg = g_V + ((size_t)b * SEQ + gcc) * DD;
      float part = 0.f;
#pragma unroll
      for (int i = 0; i < 4; i++) {
        part += Qrow[d0a + i] * Kg[d0a + i];
        part += Qrow[d0b + i] * Kg[d0b + i];
      }
      part += __shfl_xor_sync(0xffffffffu, part, 1);
      part += __shfl_xor_sync(0xffffffffu, part, 2);
      part += __shfl_xor_sync(0xffffffffu, part, 4);
      float sg = part * 0.125f;
      float mn = fmaxf(M, sg);
      float cw = __expf(M - mn);
      float pg = __expf(sg - mn);
      L = L * cw + pg;
      Aa.x = Aa.x * cw + pg * Vg[d0a + 0];
      Aa.y = Aa.y * cw + pg * Vg[d0a + 1];
      Aa.z = Aa.z * cw + pg * Vg[d0a + 2];
      Aa.w = Aa.w * cw + pg * Vg[d0a + 3];
      Ab.x = Ab.x * cw + pg * Vg[d0b + 0];
      Ab.y = Ab.y * cw + pg * Vg[d0b + 1];
      Ab.z = Ab.z * cw + pg * Vg[d0b + 2];
      Ab.w = Ab.w * cw + pg * Vg[d0b + 3];
      M = mn;
    }
  }

  const float inv = 1.f / L;
  float* orow = out + browoff * DD;
  *(float4*)&orow[d0a] = make_float4(Aa.x * inv, Aa.y * inv, Aa.z * inv, Aa.w * inv);
  *(float4*)&orow[d0b] = make_float4(Ab.x * inv, Ab.y * inv, Ab.z * inv, Ab.w * inv);
}

// ---------------------------------------------------------------------------
extern "C" void kernel_launch(void* const* d_in, const int* in_sizes, int n_in,
                              void* d_out, int out_size) {
  const float* q  = (const float*)d_in[0];
  const float* k  = (const float*)d_in[1];
  const float* v  = (const float*)d_in[2];
  const float* Wq = (const float*)d_in[3];
  const float* bq = (const float*)d_in[4];
  const float* Wk = (const float*)d_in[5];
  const float* bk = (const float*)d_in[6];
  const float* Wv = (const float*)d_in[7];
  const float* bv = (const float*)d_in[8];
  float* out = (float*)d_out;

  int gr[3], gc[3];
  compute_mask_pairs_h(gr, gc);

  dim3 pg(64, 1, 3);
  proj_kernel<<<pg, 256>>>(q, k, v, Wq, bq, Wk, bk, Wv, bv);
  attn_split_kernel<<<S_SPLIT * BATCH * (SEQ / QT), 256>>>();
  combine_kernel<<<BATCH * (SEQ / QT), 256>>>(out, gr[0], gc[0], gr[1], gc[1],
                                              gr[2], gc[2]);
}

// round 3
// speedup vs baseline: 1.8261x; 1.1387x over previous
#include <cuda_runtime.h>
#include <stdint.h>
#include <math.h>

#define BATCH 4
#define SEQ   2048
#define DIN   1024
#define DD    64
#define QT    32
#define KT    64
#define S_SPLIT 4
#define NEGF  -1e30f

// ---------------------------------------------------------------------------
// Device scratch (no cudaMalloc allowed)
// ---------------------------------------------------------------------------
__device__ float g_Q[BATCH * SEQ * DD];
__device__ float g_K[BATCH * SEQ * DD];
__device__ float g_V[BATCH * SEQ * DD];
__device__ float g_pacc[S_SPLIT * BATCH * SEQ * DD];
__device__ float g_pm[S_SPLIT * BATCH * SEQ];
__device__ float g_pl[S_SPLIT * BATCH * SEQ];

// ---------------------------------------------------------------------------
// Host-side replication of np.random.default_rng(0) mask-index generation
// ---------------------------------------------------------------------------
struct u128h { uint64_t hi, lo; };

static inline uint64_t mulhi64_h(uint64_t a, uint64_t b) {
  uint64_t al = (uint32_t)a, ah = a >> 32, bl = (uint32_t)b, bh = b >> 32;
  uint64_t p0 = al * bl, p1 = al * bh, p2 = ah * bl, p3 = ah * bh;
  uint64_t mid = (p0 >> 32) + (uint32_t)p1 + (uint32_t)p2;
  return p3 + (p1 >> 32) + (p2 >> 32) + (mid >> 32);
}

struct PCG64H {
  u128h state, inc;
  int has_uint32;
  uint32_t uinteger;
};

static inline void pcg_step_h(PCG64H* p) {
  const uint64_t mhi = 2549297995355413924ULL, mlo = 4865540595714422341ULL;
  u128h s = p->state, r;
  r.lo = s.lo * mlo;
  r.hi = mulhi64_h(s.lo, mlo) + s.lo * mhi + s.hi * mlo;
  uint64_t lo = r.lo + p->inc.lo;
  r.hi += p->inc.hi + (lo < r.lo);
  r.lo = lo;
  p->state = r;
}

static inline uint64_t rotr64_h(uint64_t v, unsigned r) {
  r &= 63u;
  return r ? ((v >> r) | (v << (64 - r))) : v;
}

static inline uint64_t pcg_next64_h(PCG64H* p) {
  pcg_step_h(p);
  return rotr64_h(p->state.hi ^ p->state.lo, (unsigned)(p->state.hi >> 58));
}

static inline uint32_t pcg_next32_h(PCG64H* p) {
  if (p->has_uint32) { p->has_uint32 = 0; return p->uinteger; }
  uint64_t n = pcg_next64_h(p);
  p->has_uint32 = 1;
  p->uinteger = (uint32_t)(n >> 32);
  return (uint32_t)n;
}

static void seedseq0_state_h(uint64_t out[4]) {
  const uint32_t INIT_A = 0x43b0d7e5u, MULT_A = 0x931e8875u;
  const uint32_t INIT_B = 0x8b51f9ddu, MULT_B = 0x58f38dedu;
  const uint32_t MIX_L = 0xca01f9ddu, MIX_R = 0x4973f715u;
  uint32_t pool[4];
  uint32_t hc = INIT_A;
  for (int i = 0; i < 4; i++) {
    uint32_t v = 0u;
    v ^= hc; hc *= MULT_A; v *= hc; v ^= v >> 16;
    pool[i] = v;
  }
  for (int s = 0; s < 4; s++) {
    for (int d = 0; d < 4; d++) {
      if (s == d) continue;
      uint32_t v = pool[s];
      v ^= hc; hc *= MULT_A; v *= hc; v ^= v >> 16;
      uint32_t r = (pool[d] * MIX_L) ^ (v * MIX_R);
      r ^= r >> 16;
      pool[d] = r;
    }
  }
  uint32_t hcb = INIT_B;
  uint32_t st[8];
  for (int i = 0; i < 8; i++) {
    uint32_t dv = pool[i & 3];
    dv ^= hcb; hcb *= MULT_B; dv ^= 0; dv *= hcb; dv ^= dv >> 16;
    st[i] = dv;
  }
  for (int k2 = 0; k2 < 4; k2++)
    out[k2] = (uint64_t)st[2 * k2] | ((uint64_t)st[2 * k2 + 1] << 32);
}

static inline uint64_t lemire32_h(PCG64H* p, uint32_t rng) {
  if (rng == 0) return 0;
  const uint32_t rng_excl = rng + 1;
  uint64_t m = (uint64_t)pcg_next32_h(p) * (uint64_t)rng_excl;
  uint32_t leftover = (uint32_t)m;
  if (leftover < rng_excl) {
    const uint32_t threshold = (uint32_t)(0xFFFFFFFFu - rng) % rng_excl;
    while (leftover < threshold) {
      m = (uint64_t)pcg_next32_h(p) * (uint64_t)rng_excl;
      leftover = (uint32_t)m;
    }
  }
  return m >> 32;
}

static void choice3_2048_h(PCG64H* p, int64_t idx[3]) {
  const int size = 3, pop = 2048;
  const uint64_t mask = 3;
  uint64_t hset[4] = {~0ull, ~0ull, ~0ull, ~0ull};
  for (int j = pop - size; j < pop; j++) {
    uint64_t val = lemire32_h(p, (uint32_t)j);
    uint64_t loc = val & mask;
    while (hset[loc] != ~0ull && hset[loc] != val) loc = (loc + 1) & mask;
    if (hset[loc] == ~0ull) {
      hset[loc] = val;
      idx[j - pop + size] = (int64_t)val;
    } else {
      loc = (uint64_t)j & mask;
      while (hset[loc] != ~0ull) loc = (loc + 1) & mask;
      hset[loc] = (uint64_t)j;
      idx[j - pop + size] = (int64_t)j;
    }
  }
  for (int i = size - 1; i >= 1; i--) {
    uint64_t jj = lemire32_h(p, (uint32_t)i);
    if ((int)jj != i) {
      int64_t t = idx[i]; idx[i] = idx[(int)jj]; idx[(int)jj] = t;
    }
  }
}

static void compute_mask_pairs_h(int gr[3], int gc[3]) {
  uint64_t sd[4];
  seedseq0_state_h(sd);
  PCG64H rng;
  rng.inc.hi = (sd[2] << 1) | (sd[3] >> 63);
  rng.inc.lo = (sd[3] << 1) | 1ull;
  rng.state.hi = 0; rng.state.lo = 0;
  pcg_step_h(&rng);
  uint64_t lo = rng.state.lo + sd[1];
  rng.state.hi += sd[0] + (lo < rng.state.lo);
  rng.state.lo = lo;
  pcg_step_h(&rng);
  rng.has_uint32 = 0; rng.uinteger = 0;

  int64_t rows[3], cols[3];
  choice3_2048_h(&rng, rows);
  choice3_2048_h(&rng, cols);
  for (int i = 0; i < 3; i++) { gr[i] = (int)rows[i]; gc[i] = (int)cols[i]; }
}

// ---------------------------------------------------------------------------
// tf32 helpers
// ---------------------------------------------------------------------------
__device__ __forceinline__ float to_tf32(float x) {
  float r;
  asm("cvt.rna.tf32.f32 %0, %1;" : "=f"(r) : "f"(x));
  return r;
}

__device__ __forceinline__ void mma_tf32(float& d0, float& d1, float& d2,
                                         float& d3, float a0, float a1,
                                         float a2, float a3, float b0,
                                         float b1) {
  asm volatile(
      "mma.sync.aligned.m16n8k8.row.col.f32.tf32.tf32.f32 "
      "{%0,%1,%2,%3},{%4,%5,%6,%7},{%8,%9},{%0,%1,%2,%3};"
      : "+f"(d0), "+f"(d1), "+f"(d2), "+f"(d3)
      : "r"(__float_as_uint(a0)), "r"(__float_as_uint(a1)),
        "r"(__float_as_uint(a2)), "r"(__float_as_uint(a3)),
        "r"(__float_as_uint(b0)), "r"(__float_as_uint(b1)));
}

// ---------------------------------------------------------------------------
// Projection GEMM on tensor cores via 3xTF32 (hi*hi + lo*hi + hi*lo).
// out[m,n] = sum_k A[m,k]*W[k,n] + b[n].  M=8192, K=1024, N=64.
// CTA: 128 threads (4 warps), tile 64(m) x 64(n), K-chunk 32.
// Warp w: rows w*16..w*16+15; 8 n-blocks of m16n8k8.
// Grid: (128 m-tiles, 3 matrices).
// ---------------------------------------------------------------------------
__global__ __launch_bounds__(128) void proj_kernel(
    const float* __restrict__ in_q, const float* __restrict__ in_k,
    const float* __restrict__ in_v,
    const float* __restrict__ Wq, const float* __restrict__ bq,
    const float* __restrict__ Wk, const float* __restrict__ bk,
    const float* __restrict__ Wv, const float* __restrict__ bv) {
  const float* A; const float* W; const float* bias; float* out;
  int z = blockIdx.y;
  if (z == 0)      { A = in_q; W = Wq; bias = bq; out = g_Q; }
  else if (z == 1) { A = in_k; W = Wk; bias = bk; out = g_K; }
  else             { A = in_v; W = Wv; bias = bv; out = g_V; }

  // strides chosen for conflict-free fragment loads:
  // A: bank = (4g + tig) all-distinct with stride 36
  // W: bank = (8*tig + g) all-distinct with stride 72
  __shared__ float Ahs[64 * 36];
  __shared__ float Als[64 * 36];
  __shared__ float Whs[32 * 72];
  __shared__ float Wls[32 * 72];

  const int t = threadIdx.x;
  const int w = t >> 5;
  const int lane = t & 31;
  const int g = lane >> 2;      // 0..7
  const int tig = lane & 3;     // 0..3
  const int m0 = blockIdx.x * 64;
  const int mw = w * 16;

  float acc[8][4];
#pragma unroll
  for (int nb = 0; nb < 8; nb++)
#pragma unroll
    for (int i = 0; i < 4; i++) acc[nb][i] = 0.f;

  for (int k0 = 0; k0 < DIN; k0 += 32) {
    __syncthreads();
    // Load + convert A chunk 64x32 (512 float4, 4 per thread)
#pragma unroll
    for (int i = 0; i < 4; i++) {
      int fidx = t + i * 128;
      int row = fidx >> 3, c4 = fidx & 7;
      float4 v = *(const float4*)&A[(size_t)(m0 + row) * DIN + k0 + c4 * 4];
      float4 h, l;
      h.x = to_tf32(v.x); l.x = to_tf32(v.x - h.x);
      h.y = to_tf32(v.y); l.y = to_tf32(v.y - h.y);
      h.z = to_tf32(v.z); l.z = to_tf32(v.z - h.z);
      h.w = to_tf32(v.w); l.w = to_tf32(v.w - h.w);
      *(float4*)&Ahs[row * 36 + c4 * 4] = h;
      *(float4*)&Als[row * 36 + c4 * 4] = l;
    }
    // Load + convert W chunk 32x64 (512 float4, 4 per thread)
#pragma unroll
    for (int i = 0; i < 4; i++) {
      int fidx = t + i * 128;
      int row = fidx >> 4, c4 = fidx & 15;
      float4 v = *(const float4*)&W[(size_t)(k0 + row) * DD + c4 * 4];
      float4 h, l;
      h.x = to_tf32(v.x); l.x = to_tf32(v.x - h.x);
      h.y = to_tf32(v.y); l.y = to_tf32(v.y - h.y);
      h.z = to_tf32(v.z); l.z = to_tf32(v.z - h.z);
      h.w = to_tf32(v.w); l.w = to_tf32(v.w - h.w);
      *(float4*)&Whs[row * 72 + c4 * 4] = h;
      *(float4*)&Wls[row * 72 + c4 * 4] = l;
    }
    __syncthreads();

    // Preload A fragments for all 4 k-steps (hi and lo)
    float ah[4][4], al[4][4];
#pragma unroll
    for (int ks = 0; ks < 4; ks++) {
      int c = ks * 8 + tig;
      ah[ks][0] = Ahs[(mw + g) * 36 + c];
      ah[ks][1] = Ahs[(mw + g + 8) * 36 + c];
      ah[ks][2] = Ahs[(mw + g) * 36 + c + 4];
      ah[ks][3] = Ahs[(mw + g + 8) * 36 + c + 4];
      al[ks][0] = Als[(mw + g) * 36 + c];
      al[ks][1] = Als[(mw + g + 8) * 36 + c];
      al[ks][2] = Als[(mw + g) * 36 + c + 4];
      al[ks][3] = Als[(mw + g + 8) * 36 + c + 4];
    }

#pragma unroll
    for (int nb = 0; nb < 8; nb++) {
      float bh[4][2], bl[4][2];
#pragma unroll
      for (int ks = 0; ks < 4; ks++) {
        int r0 = ks * 8 + tig;
        int cc = nb * 8 + g;
        bh[ks][0] = Whs[r0 * 72 + cc];
        bh[ks][1] = Whs[(r0 + 4) * 72 + cc];
        bl[ks][0] = Wls[r0 * 72 + cc];
        bl[ks][1] = Wls[(r0 + 4) * 72 + cc];
      }
#pragma unroll
      for (int ks = 0; ks < 4; ks++) {
        mma_tf32(acc[nb][0], acc[nb][1], acc[nb][2], acc[nb][3],
                 ah[ks][0], ah[ks][1], ah[ks][2], ah[ks][3],
                 bh[ks][0], bh[ks][1]);
        mma_tf32(acc[nb][0], acc[nb][1], acc[nb][2], acc[nb][3],
                 al[ks][0], al[ks][1], al[ks][2], al[ks][3],
                 bh[ks][0], bh[ks][1]);
        mma_tf32(acc[nb][0], acc[nb][1], acc[nb][2], acc[nb][3],
                 ah[ks][0], ah[ks][1], ah[ks][2], ah[ks][3],
                 bl[ks][0], bl[ks][1]);
      }
    }
  }

  // Epilogue: D layout c0:(g, tig*2) c1:(g, tig*2+1) c2:(g+8,..) c3:(g+8,..+1)
#pragma unroll
  for (int nb = 0; nb < 8; nb++) {
    int n = nb * 8 + tig * 2;
    float b0v = bias[n], b1v = bias[n + 1];
    float2 o0 = make_float2(acc[nb][0] + b0v, acc[nb][1] + b1v);
    float2 o1 = make_float2(acc[nb][2] + b0v, acc[nb][3] + b1v);
    *(float2*)&out[(size_t)(m0 + mw + g) * DD + n] = o0;
    *(float2*)&out[(size_t)(m0 + mw + g + 8) * DD + n] = o1;
  }
}

// ---------------------------------------------------------------------------
// Flash attention, split-K x S_SPLIT, fp32. Causal masking only; global-token
// corrections are applied in combine_kernel.
// ---------------------------------------------------------------------------
__global__ __launch_bounds__(256) void attn_split_kernel() {
  const int bid = blockIdx.x;
  const int s = bid >> 8;
  const int rest = bid & 255;
  const int b = rest >> 6;
  const int qt = rest & 63;
  const int qr0 = qt * QT;
  const int T = (qt >> 1) + 1;
  const int t0 = (s * T) / S_SPLIT;
  const int t1 = ((s + 1) * T) / S_SPLIT;

  const int t = threadIdx.x;
  const int r = t >> 3;
  const int sub = t & 7;
  const int rg = qr0 + r;
  const int d0a = sub * 4;
  const int d0b = 32 + sub * 4;

  const size_t prow = ((size_t)s * BATCH + b) * SEQ + qr0 + r;
  float* paccRow = g_pacc + prow * DD;

  if (t0 == t1) {
    if (sub == 0) { g_pm[prow] = NEGF; g_pl[prow] = 0.f; }
    *(float4*)&paccRow[d0a] = make_float4(0.f, 0.f, 0.f, 0.f);
    *(float4*)&paccRow[d0b] = make_float4(0.f, 0.f, 0.f, 0.f);
    return;
  }

  const float* __restrict__ Qb = g_Q + (size_t)b * SEQ * DD;
  const float* __restrict__ Kb = g_K + (size_t)b * SEQ * DD;
  const float* __restrict__ Vb = g_V + (size_t)b * SEQ * DD;

  __shared__ float Qs[QT][DD + 4];
  __shared__ float KPs[KT][DD + 4];
  __shared__ float Vs[KT][DD + 4];

  const float scale = 0.125f;

  for (int i = t; i < QT * 16; i += 256) {
    int row = i >> 4, c4 = i & 15;
    *(float4*)&Qs[row][c4 * 4] =
        *(const float4*)&Qb[(size_t)(qr0 + row) * DD + c4 * 4];
  }

  float m = NEGF, l = 0.f;
  float acc[8];
#pragma unroll
  for (int i = 0; i < 8; i++) acc[i] = 0.f;

  for (int kt = t0; kt < t1; kt++) {
    const int j0 = kt * KT;
    const bool masked = (kt == T - 1);
    __syncthreads();
    for (int i = t; i < KT * 16; i += 256) {
      int row = i >> 4, c4 = i & 15;
      *(float4*)&KPs[row][c4 * 4] =
          *(const float4*)&Kb[(size_t)(j0 + row) * DD + c4 * 4];
      *(float4*)&Vs[row][c4 * 4] =
          *(const float4*)&Vb[(size_t)(j0 + row) * DD + c4 * 4];
    }
    __syncthreads();

    float sc[8];
#pragma unroll
    for (int jj = 0; jj < 8; jj++) sc[jj] = 0.f;
#pragma unroll
    for (int d = 0; d < DD; d += 4) {
      float4 qv = *(const float4*)&Qs[r][d];
#pragma unroll
      for (int jj = 0; jj < 8; jj++) {
        float4 kv = *(const float4*)&KPs[sub + jj * 8][d];
        sc[jj] = fmaf(qv.x, kv.x, sc[jj]);
        sc[jj] = fmaf(qv.y, kv.y, sc[jj]);
        sc[jj] = fmaf(qv.z, kv.z, sc[jj]);
        sc[jj] = fmaf(qv.w, kv.w, sc[jj]);
      }
    }
    float smax = NEGF;
    if (masked) {
#pragma unroll
      for (int jj = 0; jj < 8; jj++) {
        int jg = j0 + sub + jj * 8;
        sc[jj] = (jg <= rg) ? sc[jj] * scale : NEGF;
        smax = fmaxf(smax, sc[jj]);
      }
    } else {
#pragma unroll
      for (int jj = 0; jj < 8; jj++) {
        sc[jj] *= scale;
        smax = fmaxf(smax, sc[jj]);
      }
    }
    smax = fmaxf(smax, __shfl_xor_sync(0xffffffffu, smax, 1));
    smax = fmaxf(smax, __shfl_xor_sync(0xffffffffu, smax, 2));
    smax = fmaxf(smax, __shfl_xor_sync(0xffffffffu, smax, 4));
    const float mnew = fmaxf(m, smax);
    const float corr = __expf(m - mnew);

    float p[8];
    float psum = 0.f;
#pragma unroll
    for (int jj = 0; jj < 8; jj++) {
      p[jj] = __expf(sc[jj] - mnew);
      psum += p[jj];
    }
    psum += __shfl_xor_sync(0xffffffffu, psum, 1);
    psum += __shfl_xor_sync(0xffffffffu, psum, 2);
    psum += __shfl_xor_sync(0xffffffffu, psum, 4);
    l = l * corr + psum;
    m = mnew;
#pragma unroll
    for (int i = 0; i < 8; i++) acc[i] *= corr;

    __syncthreads();
#pragma unroll
    for (int jj = 0; jj < 8; jj++) KPs[r][sub + jj * 8] = p[jj];
    __syncthreads();

#pragma unroll
    for (int j = 0; j < KT; j += 4) {
      float4 pv = *(const float4*)&KPs[r][j];
      float pvals[4] = {pv.x, pv.y, pv.z, pv.w};
#pragma unroll
      for (int u = 0; u < 4; u++) {
        float pj = pvals[u];
        float4 va = *(const float4*)&Vs[j + u][d0a];
        float4 vb = *(const float4*)&Vs[j + u][d0b];
        acc[0] = fmaf(pj, va.x, acc[0]);
        acc[1] = fmaf(pj, va.y, acc[1]);
        acc[2] = fmaf(pj, va.z, acc[2]);
        acc[3] = fmaf(pj, va.w, acc[3]);
        acc[4] = fmaf(pj, vb.x, acc[4]);
        acc[5] = fmaf(pj, vb.y, acc[5]);
        acc[6] = fmaf(pj, vb.z, acc[6]);
        acc[7] = fmaf(pj, vb.w, acc[7]);
      }
    }
  }

  if (sub == 0) { g_pm[prow] = m; g_pl[prow] = l; }
  *(float4*)&paccRow[d0a] = make_float4(acc[0], acc[1], acc[2], acc[3]);
  *(float4*)&paccRow[d0b] = make_float4(acc[4], acc[5], acc[6], acc[7]);
}

// ---------------------------------------------------------------------------
// Combine splits + apply global-token corrections + normalize + write out.
// ---------------------------------------------------------------------------
__global__ __launch_bounds__(256) void combine_kernel(
    float* __restrict__ out,
    int gr0, int gc0, int gr1, int gc1, int gr2, int gc2) {
  const int bid = blockIdx.x;
  const int b = bid >> 6;
  const int rt = bid & 63;
  const int t = threadIdx.x;
  const int r = t >> 3;
  const int sub = t & 7;
  const int row = rt * 32 + r;
  const int d0a = sub * 4;
  const int d0b = 32 + sub * 4;
  const size_t browoff = (size_t)b * SEQ + row;

  float ms[S_SPLIT], ls[S_SPLIT];
  float M = NEGF;
#pragma unroll
  for (int s = 0; s < S_SPLIT; s++) {
    size_t prow = ((size_t)s * BATCH + b) * SEQ + row;
    ms[s] = g_pm[prow];
    ls[s] = g_pl[prow];
    M = fmaxf(M, ms[s]);
  }
  float L = 0.f;
  float4 Aa = make_float4(0.f, 0.f, 0.f, 0.f);
  float4 Ab = make_float4(0.f, 0.f, 0.f, 0.f);
#pragma unroll
  for (int s = 0; s < S_SPLIT; s++) {
    size_t prow = ((size_t)s * BATCH + b) * SEQ + row;
    float w = __expf(ms[s] - M);
    L += ls[s] * w;
    const float* pr = g_pacc + prow * DD;
    float4 pa = *(const float4*)&pr[d0a];
    float4 pb = *(const float4*)&pr[d0b];
    Aa.x += w * pa.x; Aa.y += w * pa.y; Aa.z += w * pa.z; Aa.w += w * pa.w;
    Ab.x += w * pb.x; Ab.y += w * pb.y; Ab.z += w * pb.z; Ab.w += w * pb.w;
  }

  const int grs[3] = {gr0, gr1, gr2};
  const int gcs[3] = {gc0, gc1, gc2};
  const float* __restrict__ Qrow = g_Q + browoff * DD;
#pragma unroll
  for (int g = 0; g < 3; g++) {
    int grr = grs[g], gcc = gcs[g];
    if (row == grr && gcc > grr) {
      const float* Kg = g_K + ((size_t)b * SEQ + gcc) * DD;
      const float* Vg = g_V + ((size_t)b * SEQ + gcc) * DD;
      float part = 0.f;
#pragma unroll
      for (int i = 0; i < 4; i++) {
        part += Qrow[d0a + i] * Kg[d0a + i];
        part += Qrow[d0b + i] * Kg[d0b + i];
      }
      part += __shfl_xor_sync(0xffffffffu, part, 1);
      part += __shfl_xor_sync(0xffffffffu, part, 2);
      part += __shfl_xor_sync(0xffffffffu, part, 4);
      float sg = part * 0.125f;
      float mn = fmaxf(M, sg);
      float cw = __expf(M - mn);
      float pg = __expf(sg - mn);
      L = L * cw + pg;
      Aa.x = Aa.x * cw + pg * Vg[d0a + 0];
      Aa.y = Aa.y * cw + pg * Vg[d0a + 1];
      Aa.z = Aa.z * cw + pg * Vg[d0a + 2];
      Aa.w = Aa.w * cw + pg * Vg[d0a + 3];
      Ab.x = Ab.x * cw + pg * Vg[d0b + 0];
      Ab.y = Ab.y * cw + pg * Vg[d0b + 1];
      Ab.z = Ab.z * cw + pg * Vg[d0b + 2];
      Ab.w = Ab.w * cw + pg * Vg[d0b + 3];
      M = mn;
    }
  }

  const float inv = 1.f / L;
  float* orow = out + browoff * DD;
  *(float4*)&orow[d0a] = make_float4(Aa.x * inv, Aa.y * inv, Aa.z * inv, Aa.w * inv);
  *(float4*)&orow[d0b] = make_float4(Ab.x * inv, Ab.y * inv, Ab.z * inv, Ab.w * inv);
}

// ---------------------------------------------------------------------------
extern "C" void kernel_launch(void* const* d_in, const int* in_sizes, int n_in,
                              void* d_out, int out_size) {
  const float* q  = (const float*)d_in[0];
  const float* k  = (const float*)d_in[1];
  const float* v  = (const float*)d_in[2];
  const float* Wq = (const float*)d_in[3];
  const float* bq = (const float*)d_in[4];
  const float* Wk = (const float*)d_in[5];
  const float* bk = (const float*)d_in[6];
  const float* Wv = (const float*)d_in[7];
  const float* bv = (const float*)d_in[8];
  float* out = (float*)d_out;

  int gr[3], gc[3];
  compute_mask_pairs_h(gr, gc);

  dim3 pg(128, 3);
  proj_kernel<<<pg, 128>>>(q, k, v, Wq, bq, Wk, bk, Wv, bv);
  attn_split_kernel<<<S_SPLIT * BATCH * (SEQ / QT), 256>>>();
  combine_kernel<<<BATCH * (SEQ / QT), 256>>>(out, gr[0], gc[0], gr[1], gc[1],
                                              gr[2], gc[2]);
}

// round 4
// speedup vs baseline: 3.3438x; 1.8311x over previous
#include <cuda_runtime.h>
#include <stdint.h>
#include <math.h>

#define BATCH 4
#define SEQ   2048
#define DIN   1024
#define DD    64
#define S_SPLIT 4
#define NEGF  -1e30f

// ---------------------------------------------------------------------------
// Device scratch (no cudaMalloc allowed)
// ---------------------------------------------------------------------------
__device__ float g_Q[BATCH * SEQ * DD];
__device__ float g_K[BATCH * SEQ * DD];
__device__ float g_V[BATCH * SEQ * DD];
__device__ float g_pacc[S_SPLIT * BATCH * SEQ * DD];
__device__ float g_pm[S_SPLIT * BATCH * SEQ];
__device__ float g_pl[S_SPLIT * BATCH * SEQ];

// ---------------------------------------------------------------------------
// Host-side replication of np.random.default_rng(0) mask-index generation
// ---------------------------------------------------------------------------
struct u128h { uint64_t hi, lo; };

static inline uint64_t mulhi64_h(uint64_t a, uint64_t b) {
  uint64_t al = (uint32_t)a, ah = a >> 32, bl = (uint32_t)b, bh = b >> 32;
  uint64_t p0 = al * bl, p1 = al * bh, p2 = ah * bl, p3 = ah * bh;
  uint64_t mid = (p0 >> 32) + (uint32_t)p1 + (uint32_t)p2;
  return p3 + (p1 >> 32) + (p2 >> 32) + (mid >> 32);
}

struct PCG64H {
  u128h state, inc;
  int has_uint32;
  uint32_t uinteger;
};

static inline void pcg_step_h(PCG64H* p) {
  const uint64_t mhi = 2549297995355413924ULL, mlo = 4865540595714422341ULL;
  u128h s = p->state, r;
  r.lo = s.lo * mlo;
  r.hi = mulhi64_h(s.lo, mlo) + s.lo * mhi + s.hi * mlo;
  uint64_t lo = r.lo + p->inc.lo;
  r.hi += p->inc.hi + (lo < r.lo);
  r.lo = lo;
  p->state = r;
}

static inline uint64_t rotr64_h(uint64_t v, unsigned r) {
  r &= 63u;
  return r ? ((v >> r) | (v << (64 - r))) : v;
}

static inline uint64_t pcg_next64_h(PCG64H* p) {
  pcg_step_h(p);
  return rotr64_h(p->state.hi ^ p->state.lo, (unsigned)(p->state.hi >> 58));
}

static inline uint32_t pcg_next32_h(PCG64H* p) {
  if (p->has_uint32) { p->has_uint32 = 0; return p->uinteger; }
  uint64_t n = pcg_next64_h(p);
  p->has_uint32 = 1;
  p->uinteger = (uint32_t)(n >> 32);
  return (uint32_t)n;
}

static void seedseq0_state_h(uint64_t out[4]) {
  const uint32_t INIT_A = 0x43b0d7e5u, MULT_A = 0x931e8875u;
  const uint32_t INIT_B = 0x8b51f9ddu, MULT_B = 0x58f38dedu;
  const uint32_t MIX_L = 0xca01f9ddu, MIX_R = 0x4973f715u;
  uint32_t pool[4];
  uint32_t hc = INIT_A;
  for (int i = 0; i < 4; i++) {
    uint32_t v = 0u;
    v ^= hc; hc *= MULT_A; v *= hc; v ^= v >> 16;
    pool[i] = v;
  }
  for (int s = 0; s < 4; s++) {
    for (int d = 0; d < 4; d++) {
      if (s == d) continue;
      uint32_t v = pool[s];
      v ^= hc; hc *= MULT_A; v *= hc; v ^= v >> 16;
      uint32_t r = (pool[d] * MIX_L) ^ (v * MIX_R);
      r ^= r >> 16;
      pool[d] = r;
    }
  }
  uint32_t hcb = INIT_B;
  uint32_t st[8];
  for (int i = 0; i < 8; i++) {
    uint32_t dv = pool[i & 3];
    dv ^= hcb; hcb *= MULT_B; dv *= hcb; dv ^= dv >> 16;
    st[i] = dv;
  }
  for (int k2 = 0; k2 < 4; k2++)
    out[k2] = (uint64_t)st[2 * k2] | ((uint64_t)st[2 * k2 + 1] << 32);
}

static inline uint64_t lemire32_h(PCG64H* p, uint32_t rng) {
  if (rng == 0) return 0;
  const uint32_t rng_excl = rng + 1;
  uint64_t m = (uint64_t)pcg_next32_h(p) * (uint64_t)rng_excl;
  uint32_t leftover = (uint32_t)m;
  if (leftover < rng_excl) {
    const uint32_t threshold = (uint32_t)(0xFFFFFFFFu - rng) % rng_excl;
    while (leftover < threshold) {
      m = (uint64_t)pcg_next32_h(p) * (uint64_t)rng_excl;
      leftover = (uint32_t)m;
    }
  }
  return m >> 32;
}

static void choice3_2048_h(PCG64H* p, int64_t idx[3]) {
  const int size = 3, pop = 2048;
  const uint64_t mask = 3;
  uint64_t hset[4] = {~0ull, ~0ull, ~0ull, ~0ull};
  for (int j = pop - size; j < pop; j++) {
    uint64_t val = lemire32_h(p, (uint32_t)j);
    uint64_t loc = val & mask;
    while (hset[loc] != ~0ull && hset[loc] != val) loc = (loc + 1) & mask;
    if (hset[loc] == ~0ull) {
      hset[loc] = val;
      idx[j - pop + size] = (int64_t)val;
    } else {
      loc = (uint64_t)j & mask;
      while (hset[loc] != ~0ull) loc = (loc + 1) & mask;
      hset[loc] = (uint64_t)j;
      idx[j - pop + size] = (int64_t)j;
    }
  }
  for (int i = size - 1; i >= 1; i--) {
    uint64_t jj = lemire32_h(p, (uint32_t)i);
    if ((int)jj != i) {
      int64_t t = idx[i]; idx[i] = idx[(int)jj]; idx[(int)jj] = t;
    }
  }
}

static void compute_mask_pairs_h(int gr[3], int gc[3]) {
  uint64_t sd[4];
  seedseq0_state_h(sd);
  PCG64H rng;
  rng.inc.hi = (sd[2] << 1) | (sd[3] >> 63);
  rng.inc.lo = (sd[3] << 1) | 1ull;
  rng.state.hi = 0; rng.state.lo = 0;
  pcg_step_h(&rng);
  uint64_t lo = rng.state.lo + sd[1];
  rng.state.hi += sd[0] + (lo < rng.state.lo);
  rng.state.lo = lo;
  pcg_step_h(&rng);
  rng.has_uint32 = 0; rng.uinteger = 0;

  int64_t rows[3], cols[3];
  choice3_2048_h(&rng, rows);
  choice3_2048_h(&rng, cols);
  for (int i = 0; i < 3; i++) { gr[i] = (int)rows[i]; gc[i] = (int)cols[i]; }
}

// ---------------------------------------------------------------------------
// tf32 helpers
// ---------------------------------------------------------------------------
__device__ __forceinline__ float to_tf32(float x) {
  float r;
  asm("cvt.rna.tf32.f32 %0, %1;" : "=f"(r) : "f"(x));
  return r;
}

__device__ __forceinline__ void mma_tf32(float& d0, float& d1, float& d2,
                                         float& d3, float a0, float a1,
                                         float a2, float a3, float b0,
                                         float b1) {
  asm volatile(
      "mma.sync.aligned.m16n8k8.row.col.f32.tf32.tf32.f32 "
      "{%0,%1,%2,%3},{%4,%5,%6,%7},{%8,%9},{%0,%1,%2,%3};"
      : "+f"(d0), "+f"(d1), "+f"(d2), "+f"(d3)
      : "r"(__float_as_uint(a0)), "r"(__float_as_uint(a1)),
        "r"(__float_as_uint(a2)), "r"(__float_as_uint(a3)),
        "r"(__float_as_uint(b0)), "r"(__float_as_uint(b1)));
}

// ---------------------------------------------------------------------------
// Projection GEMM on tensor cores via 3xTF32, with register prefetch of the
// next K-chunk to hide global-load latency (grid is only ~2.6 CTAs/SM).
// CTA: 128 threads (4 warps), tile 64(m) x 64(n), K-chunk 32.
// ---------------------------------------------------------------------------
__global__ __launch_bounds__(128) void proj_kernel(
    const float* __restrict__ in_q, const float* __restrict__ in_k,
    const float* __restrict__ in_v,
    const float* __restrict__ Wq, const float* __restrict__ bq,
    const float* __restrict__ Wk, const float* __restrict__ bk,
    const float* __restrict__ Wv, const float* __restrict__ bv) {
  const float* A; const float* W; const float* bias; float* out;
  int z = blockIdx.y;
  if (z == 0)      { A = in_q; W = Wq; bias = bq; out = g_Q; }
  else if (z == 1) { A = in_k; W = Wk; bias = bk; out = g_K; }
  else             { A = in_v; W = Wv; bias = bv; out = g_V; }

  __shared__ float Ahs[64 * 36];
  __shared__ float Als[64 * 36];
  __shared__ float Whs[32 * 72];
  __shared__ float Wls[32 * 72];

  const int t = threadIdx.x;
  const int w = t >> 5;
  const int lane = t & 31;
  const int g = lane >> 2;
  const int tig = lane & 3;
  const int m0 = blockIdx.x * 64;
  const int mw = w * 16;

  float acc[8][4];
#pragma unroll
  for (int nb = 0; nb < 8; nb++)
#pragma unroll
    for (int i = 0; i < 4; i++) acc[nb][i] = 0.f;

  // prefetch chunk 0 into registers
  float4 arg[4], wrg[4];
#pragma unroll
  for (int i = 0; i < 4; i++) {
    int fidx = t + i * 128;
    arg[i] = *(const float4*)&A[(size_t)(m0 + (fidx >> 3)) * DIN +
                                (fidx & 7) * 4];
    wrg[i] = *(const float4*)&W[(size_t)(fidx >> 4) * DD + (fidx & 15) * 4];
  }

  for (int k0 = 0; k0 < DIN; k0 += 32) {
    // convert + store current chunk (held in regs)
#pragma unroll
    for (int i = 0; i < 4; i++) {
      int fidx = t + i * 128;
      {
        int row = fidx >> 3, c4 = (fidx & 7) * 4;
        float4 v = arg[i], h, l;
        h.x = to_tf32(v.x); l.x = to_tf32(v.x - h.x);
        h.y = to_tf32(v.y); l.y = to_tf32(v.y - h.y);
        h.z = to_tf32(v.z); l.z = to_tf32(v.z - h.z);
        h.w = to_tf32(v.w); l.w = to_tf32(v.w - h.w);
        *(float4*)&Ahs[row * 36 + c4] = h;
        *(float4*)&Als[row * 36 + c4] = l;
      }
      {
        int row = fidx >> 4, c4 = (fidx & 15) * 4;
        float4 v = wrg[i], h, l;
        h.x = to_tf32(v.x); l.x = to_tf32(v.x - h.x);
        h.y = to_tf32(v.y); l.y = to_tf32(v.y - h.y);
        h.z = to_tf32(v.z); l.z = to_tf32(v.z - h.z);
        h.w = to_tf32(v.w); l.w = to_tf32(v.w - h.w);
        *(float4*)&Whs[row * 72 + c4] = h;
        *(float4*)&Wls[row * 72 + c4] = l;
      }
    }
    __syncthreads();

    // prefetch next chunk (latency hidden behind the MMA section)
    if (k0 + 32 < DIN) {
#pragma unroll
      for (int i = 0; i < 4; i++) {
        int fidx = t + i * 128;
        arg[i] = *(const float4*)&A[(size_t)(m0 + (fidx >> 3)) * DIN + k0 +
                                    32 + (fidx & 7) * 4];
        wrg[i] = *(const float4*)&W[(size_t)(k0 + 32 + (fidx >> 4)) * DD +
                                    (fidx & 15) * 4];
      }
    }

    float ah[4][4], al[4][4];
#pragma unroll
    for (int ks = 0; ks < 4; ks++) {
      int c = ks * 8 + tig;
      ah[ks][0] = Ahs[(mw + g) * 36 + c];
      ah[ks][1] = Ahs[(mw + g + 8) * 36 + c];
      ah[ks][2] = Ahs[(mw + g) * 36 + c + 4];
      ah[ks][3] = Ahs[(mw + g + 8) * 36 + c + 4];
      al[ks][0] = Als[(mw + g) * 36 + c];
      al[ks][1] = Als[(mw + g + 8) * 36 + c];
      al[ks][2] = Als[(mw + g) * 36 + c + 4];
      al[ks][3] = Als[(mw + g + 8) * 36 + c + 4];
    }

#pragma unroll
    for (int nb = 0; nb < 8; nb++) {
      float bh[4][2], bl[4][2];
#pragma unroll
      for (int ks = 0; ks < 4; ks++) {
        int r0 = ks * 8 + tig;
        int cc = nb * 8 + g;
        bh[ks][0] = Whs[r0 * 72 + cc];
        bh[ks][1] = Whs[(r0 + 4) * 72 + cc];
        bl[ks][0] = Wls[r0 * 72 + cc];
        bl[ks][1] = Wls[(r0 + 4) * 72 + cc];
      }
#pragma unroll
      for (int ks = 0; ks < 4; ks++) {
        mma_tf32(acc[nb][0], acc[nb][1], acc[nb][2], acc[nb][3],
                 ah[ks][0], ah[ks][1], ah[ks][2], ah[ks][3],
                 bh[ks][0], bh[ks][1]);
        mma_tf32(acc[nb][0], acc[nb][1], acc[nb][2], acc[nb][3],
                 al[ks][0], al[ks][1], al[ks][2], al[ks][3],
                 bh[ks][0], bh[ks][1]);
        mma_tf32(acc[nb][0], acc[nb][1], acc[nb][2], acc[nb][3],
                 ah[ks][0], ah[ks][1], ah[ks][2], ah[ks][3],
                 bl[ks][0], bl[ks][1]);
      }
    }
    __syncthreads();
  }

#pragma unroll
  for (int nb = 0; nb < 8; nb++) {
    int n = nb * 8 + tig * 2;
    float b0v = bias[n], b1v = bias[n + 1];
    float2 o0 = make_float2(acc[nb][0] + b0v, acc[nb][1] + b1v);
    float2 o1 = make_float2(acc[nb][2] + b0v, acc[nb][3] + b1v);
    *(float2*)&out[(size_t)(m0 + mw + g) * DD + n] = o0;
    *(float2*)&out[(size_t)(m0 + mw + g + 8) * DD + n] = o1;
  }
}

// ---------------------------------------------------------------------------
// Flash attention on tensor cores (3xTF32 for Q.K^T and P.V), split-K x4.
// CTA: 128 threads (4 warps), 64 q-rows, 64-key tiles.
// Warp w: q-rows mw..mw+15. Q fragments (pre-scaled by 1/8) in registers.
// Smem (dynamic, 89,088 B): Kh/Kl/Ps stride 68 (banks 4g+tig), Vh/Vl
// stride 72 (banks 8*tig+g) — all fragment accesses conflict-free.
// Causal mask on diagonal tile only; global-token pairs fixed in combine.
// ---------------------------------------------------------------------------
__global__ __launch_bounds__(128) void attn_split_kernel() {
  extern __shared__ float sm[];
  float* Kh = sm;                       // 64*68
  float* Kl = Kh + 64 * 68;             // 64*68
  float* Ps = Kl + 64 * 68;             // 64*68 (Q staging, then P)
  float* Vh = Ps + 64 * 68;             // 64*72
  float* Vl = Vh + 64 * 72;             // 64*72

  const int bid = blockIdx.x;
  const int s = bid >> 7;
  const int rest = bid & 127;
  const int b = rest >> 5;
  const int qt = rest & 31;
  const int qr0 = qt * 64;
  const int T = qt + 1;
  const int t0 = (s * T) / S_SPLIT;
  const int t1 = ((s + 1) * T) / S_SPLIT;

  const int t = threadIdx.x;
  const int w = t >> 5;
  const int lane = t & 31;
  const int g = lane >> 2;
  const int tig = lane & 3;
  const int mw = w * 16;

  const size_t pbase = ((size_t)s * BATCH + b) * SEQ + qr0;

  if (t0 == t1) {  // empty split
    for (int i = t; i < 64 * 16; i += 128) {
      int row = i >> 4, c4 = (i & 15) * 4;
      *(float4*)&g_pacc[(pbase + row) * DD + c4] =
          make_float4(0.f, 0.f, 0.f, 0.f);
    }
    if (t < 64) { g_pm[pbase + t] = NEGF; g_pl[pbase + t] = 0.f; }
    return;
  }

  const float* __restrict__ Qb = g_Q + (size_t)b * SEQ * DD;
  const float* __restrict__ Kb = g_K + (size_t)b * SEQ * DD;
  const float* __restrict__ Vb = g_V + (size_t)b * SEQ * DD;

  // Stage Q (pre-scaled by 1/8) into Ps, then load fragments to registers.
  for (int i = t; i < 64 * 16; i += 128) {
    int row = i >> 4, c4 = (i & 15) * 4;
    float4 v = *(const float4*)&Qb[(size_t)(qr0 + row) * DD + c4];
    v.x *= 0.125f; v.y *= 0.125f; v.z *= 0.125f; v.w *= 0.125f;
    *(float4*)&Ps[row * 68 + c4] = v;
  }
  __syncthreads();

  float qh[8][4], ql[8][4];
#pragma unroll
  for (int ks = 0; ks < 8; ks++) {
    int c = ks * 8 + tig;
    float v0 = Ps[(mw + g) * 68 + c];
    float v1 = Ps[(mw + g + 8) * 68 + c];
    float v2 = Ps[(mw + g) * 68 + c + 4];
    float v3 = Ps[(mw + g + 8) * 68 + c + 4];
    qh[ks][0] = to_tf32(v0); ql[ks][0] = to_tf32(v0 - qh[ks][0]);
    qh[ks][1] = to_tf32(v1); ql[ks][1] = to_tf32(v1 - qh[ks][1]);
    qh[ks][2] = to_tf32(v2); ql[ks][2] = to_tf32(v2 - qh[ks][2]);
    qh[ks][3] = to_tf32(v3); ql[ks][3] = to_tf32(v3 - qh[ks][3]);
  }

  float m0 = NEGF, m1 = NEGF, l0 = 0.f, l1 = 0.f;
  float acc[8][4];
#pragma unroll
  for (int nb = 0; nb < 8; nb++)
#pragma unroll
    for (int i = 0; i < 4; i++) acc[nb][i] = 0.f;

  const int row0g = qr0 + mw + g;
  const int row1g = row0g + 8;

  for (int kt = t0; kt < t1; kt++) {
    const int j0 = kt * 64;
    __syncthreads();  // previous iteration's K/V reads done
    for (int i = t; i < 64 * 16; i += 128) {
      int row = i >> 4, c4 = (i & 15) * 4;
      float4 kv = *(const float4*)&Kb[(size_t)(j0 + row) * DD + c4];
      float4 h, l;
      h.x = to_tf32(kv.x); l.x = to_tf32(kv.x - h.x);
      h.y = to_tf32(kv.y); l.y = to_tf32(kv.y - h.y);
      h.z = to_tf32(kv.z); l.z = to_tf32(kv.z - h.z);
      h.w = to_tf32(kv.w); l.w = to_tf32(kv.w - h.w);
      *(float4*)&Kh[row * 68 + c4] = h;
      *(float4*)&Kl[row * 68 + c4] = l;
      float4 vv = *(const float4*)&Vb[(size_t)(j0 + row) * DD + c4];
      h.x = to_tf32(vv.x); l.x = to_tf32(vv.x - h.x);
      h.y = to_tf32(vv.y); l.y = to_tf32(vv.y - h.y);
      h.z = to_tf32(vv.z); l.z = to_tf32(vv.z - h.z);
      h.w = to_tf32(vv.w); l.w = to_tf32(vv.w - h.w);
      *(float4*)&Vh[row * 72 + c4] = h;
      *(float4*)&Vl[row * 72 + c4] = l;
    }
    __syncthreads();

    // S = Qs . K^T  (m16 q-rows x n8 keys x k8 dims)
    float sacc[8][4];
#pragma unroll
    for (int nb = 0; nb < 8; nb++)
#pragma unroll
      for (int i = 0; i < 4; i++) sacc[nb][i] = 0.f;
#pragma unroll
    for (int ks = 0; ks < 8; ks++) {
#pragma unroll
      for (int nb = 0; nb < 8; nb++) {
        int ko = ks * 8 + tig;
        int krow = (nb * 8 + g) * 68;
        float bh0 = Kh[krow + ko];
        float bh1 = Kh[krow + ko + 4];
        float bl0 = Kl[krow + ko];
        float bl1 = Kl[krow + ko + 4];
        mma_tf32(sacc[nb][0], sacc[nb][1], sacc[nb][2], sacc[nb][3],
                 qh[ks][0], qh[ks][1], qh[ks][2], qh[ks][3], bh0, bh1);
        mma_tf32(sacc[nb][0], sacc[nb][1], sacc[nb][2], sacc[nb][3],
                 ql[ks][0], ql[ks][1], ql[ks][2], ql[ks][3], bh0, bh1);
        mma_tf32(sacc[nb][0], sacc[nb][1], sacc[nb][2], sacc[nb][3],
                 qh[ks][0], qh[ks][1], qh[ks][2], qh[ks][3], bl0, bl1);
      }
    }

    if (kt == T - 1) {  // diagonal tile: causal mask
#pragma unroll
      for (int nb = 0; nb < 8; nb++) {
        int kg = j0 + nb * 8 + tig * 2;
        if (kg > row0g)     sacc[nb][0] = NEGF;
        if (kg + 1 > row0g) sacc[nb][1] = NEGF;
        if (kg > row1g)     sacc[nb][2] = NEGF;
        if (kg + 1 > row1g) sacc[nb][3] = NEGF;
      }
    }

    // online softmax (2 rows per lane)
    float mx0 = NEGF, mx1 = NEGF;
#pragma unroll
    for (int nb = 0; nb < 8; nb++) {
      mx0 = fmaxf(mx0, fmaxf(sacc[nb][0], sacc[nb][1]));
      mx1 = fmaxf(mx1, fmaxf(sacc[nb][2], sacc[nb][3]));
    }
    mx0 = fmaxf(mx0, __shfl_xor_sync(0xffffffffu, mx0, 1));
    mx0 = fmaxf(mx0, __shfl_xor_sync(0xffffffffu, mx0, 2));
    mx1 = fmaxf(mx1, __shfl_xor_sync(0xffffffffu, mx1, 1));
    mx1 = fmaxf(mx1, __shfl_xor_sync(0xffffffffu, mx1, 2));
    const float mn0 = fmaxf(m0, mx0);
    const float mn1 = fmaxf(m1, mx1);
    const float c0 = __expf(m0 - mn0);
    const float c1 = __expf(m1 - mn1);

    float s0 = 0.f, s1 = 0.f;
#pragma unroll
    for (int nb = 0; nb < 8; nb++) {
      float p00 = __expf(sacc[nb][0] - mn0);
      float p01 = __expf(sacc[nb][1] - mn0);
      float p10 = __expf(sacc[nb][2] - mn1);
      float p11 = __expf(sacc[nb][3] - mn1);
      s0 += p00 + p01;
      s1 += p10 + p11;
      *(float2*)&Ps[(mw + g) * 68 + nb * 8 + tig * 2] = make_float2(p00, p01);
      *(float2*)&Ps[(mw + g + 8) * 68 + nb * 8 + tig * 2] =
          make_float2(p10, p11);
    }
    s0 += __shfl_xor_sync(0xffffffffu, s0, 1);
    s0 += __shfl_xor_sync(0xffffffffu, s0, 2);
    s1 += __shfl_xor_sync(0xffffffffu, s1, 1);
    s1 += __shfl_xor_sync(0xffffffffu, s1, 2);
    l0 = l0 * c0 + s0;
    l1 = l1 * c1 + s1;
    m0 = mn0;
    m1 = mn1;
#pragma unroll
    for (int nb = 0; nb < 8; nb++) {
      acc[nb][0] *= c0; acc[nb][1] *= c0;
      acc[nb][2] *= c1; acc[nb][3] *= c1;
    }

    // O += P . V  (P rows are warp-private: no cross-warp sync needed)
#pragma unroll
    for (int kb = 0; kb < 8; kb++) {
      int co = kb * 8 + tig;
      float a0v = Ps[(mw + g) * 68 + co];
      float a1v = Ps[(mw + g + 8) * 68 + co];
      float a2v = Ps[(mw + g) * 68 + co + 4];
      float a3v = Ps[(mw + g + 8) * 68 + co + 4];
      float ah0 = to_tf32(a0v), al0 = to_tf32(a0v - ah0);
      float ah1 = to_tf32(a1v), al1 = to_tf32(a1v - ah1);
      float ah2 = to_tf32(a2v), al2 = to_tf32(a2v - ah2);
      float ah3 = to_tf32(a3v), al3 = to_tf32(a3v - ah3);
#pragma unroll
      for (int nb = 0; nb < 8; nb++) {
        int vr = (kb * 8 + tig) * 72 + nb * 8 + g;
        float bh0 = Vh[vr];
        float bh1 = Vh[vr + 4 * 72];
        float bl0 = Vl[vr];
        float bl1 = Vl[vr + 4 * 72];
        mma_tf32(acc[nb][0], acc[nb][1], acc[nb][2], acc[nb][3],
                 ah0, ah1, ah2, ah3, bh0, bh1);
        mma_tf32(acc[nb][0], acc[nb][1], acc[nb][2], acc[nb][3],
                 al0, al1, al2, al3, bh0, bh1);
        mma_tf32(acc[nb][0], acc[nb][1], acc[nb][2], acc[nb][3],
                 ah0, ah1, ah2, ah3, bl0, bl1);
      }
    }
  }

  const size_t r0 = pbase + mw + g;
  const size_t r1 = r0 + 8;
  if (tig == 0) {
    g_pm[r0] = m0; g_pl[r0] = l0;
    g_pm[r1] = m1; g_pl[r1] = l1;
  }
#pragma unroll
  for (int nb = 0; nb < 8; nb++) {
    int n = nb * 8 + tig * 2;
    *(float2*)&g_pacc[r0 * DD + n] = make_float2(acc[nb][0], acc[nb][1]);
    *(float2*)&g_pacc[r1 * DD + n] = make_float2(acc[nb][2], acc[nb][3]);
  }
}

// ---------------------------------------------------------------------------
// Combine splits + apply global-token corrections + normalize + write out.
// Grid: BATCH * (SEQ/32) = 256 blocks, 256 threads (r = t>>3, sub = t&7).
// ---------------------------------------------------------------------------
__global__ __launch_bounds__(256) void combine_kernel(
    float* __restrict__ out,
    int gr0, int gc0, int gr1, int gc1, int gr2, int gc2) {
  const int bid = blockIdx.x;
  const int b = bid >> 6;
  const int rt = bid & 63;
  const int t = threadIdx.x;
  const int r = t >> 3;
  const int sub = t & 7;
  const int row = rt * 32 + r;
  const int d0a = sub * 4;
  const int d0b = 32 + sub * 4;
  const size_t browoff = (size_t)b * SEQ + row;

  float ms[S_SPLIT], ls[S_SPLIT];
  float M = NEGF;
#pragma unroll
  for (int s = 0; s < S_SPLIT; s++) {
    size_t prow = ((size_t)s * BATCH + b) * SEQ + row;
    ms[s] = g_pm[prow];
    ls[s] = g_pl[prow];
    M = fmaxf(M, ms[s]);
  }
  float L = 0.f;
  float4 Aa = make_float4(0.f, 0.f, 0.f, 0.f);
  float4 Ab = make_float4(0.f, 0.f, 0.f, 0.f);
#pragma unroll
  for (int s = 0; s < S_SPLIT; s++) {
    size_t prow = ((size_t)s * BATCH + b) * SEQ + row;
    float w = __expf(ms[s] - M);
    L += ls[s] * w;
    const float* pr = g_pacc + prow * DD;
    float4 pa = *(const float4*)&pr[d0a];
    float4 pb = *(const float4*)&pr[d0b];
    Aa.x += w * pa.x; Aa.y += w * pa.y; Aa.z += w * pa.z; Aa.w += w * pa.w;
    Ab.x += w * pb.x; Ab.y += w * pb.y; Ab.z += w * pb.z; Ab.w += w * pb.w;
  }

  const int grs[3] = {gr0, gr1, gr2};
  const int gcs[3] = {gc0, gc1, gc2};
  const float* __restrict__ Qrow = g_Q + browoff * DD;
#pragma unroll
  for (int g = 0; g < 3; g++) {
    int grr = grs[g], gcc = gcs[g];
    if (row == grr && gcc > grr) {
      const float* Kg = g_K + ((size_t)b * SEQ + gcc) * DD;
      const float* Vg = g_V + ((size_t)b * SEQ + gcc) * DD;
      float part = 0.f;
#pragma unroll
      for (int i = 0; i < 4; i++) {
        part += Qrow[d0a + i] * Kg[d0a + i];
        part += Qrow[d0b + i] * Kg[d0b + i];
      }
      part += __shfl_xor_sync(0xffffffffu, part, 1);
      part += __shfl_xor_sync(0xffffffffu, part, 2);
      part += __shfl_xor_sync(0xffffffffu, part, 4);
      float sg = part * 0.125f;
      float mn = fmaxf(M, sg);
      float cw = __expf(M - mn);
      float pg = __expf(sg - mn);
      L = L * cw + pg;
      Aa.x = Aa.x * cw + pg * Vg[d0a + 0];
      Aa.y = Aa.y * cw + pg * Vg[d0a + 1];
      Aa.z = Aa.z * cw + pg * Vg[d0a + 2];
      Aa.w = Aa.w * cw + pg * Vg[d0a + 3];
      Ab.x = Ab.x * cw + pg * Vg[d0b + 0];
      Ab.y = Ab.y * cw + pg * Vg[d0b + 1];
      Ab.z = Ab.z * cw + pg * Vg[d0b + 2];
      Ab.w = Ab.w * cw + pg * Vg[d0b + 3];
      M = mn;
    }
  }

  const float inv = 1.f / L;
  float* orow = out + browoff * DD;
  *(float4*)&orow[d0a] = make_float4(Aa.x * inv, Aa.y * inv, Aa.z * inv, Aa.w * inv);
  *(float4*)&orow[d0b] = make_float4(Ab.x * inv, Ab.y * inv, Ab.z * inv, Ab.w * inv);
}

// ---------------------------------------------------------------------------
extern "C" void kernel_launch(void* const* d_in, const int* in_sizes, int n_in,
                              void* d_out, int out_size) {
  const float* q  = (const float*)d_in[0];
  const float* k  = (const float*)d_in[1];
  const float* v  = (const float*)d_in[2];
  const float* Wq = (const float*)d_in[3];
  const float* bq = (const float*)d_in[4];
  const float* Wk = (const float*)d_in[5];
  const float* bk = (const float*)d_in[6];
  const float* Wv = (const float*)d_in[7];
  const float* bv = (const float*)d_in[8];
  float* out = (float*)d_out;

  int gr[3], gc[3];
  compute_mask_pairs_h(gr, gc);

  const int ATTN_SMEM = (3 * 64 * 68 + 2 * 64 * 72) * 4;  // 89,088 B
  cudaFuncSetAttribute(attn_split_kernel,
                       cudaFuncAttributeMaxDynamicSharedMemorySize, ATTN_SMEM);

  dim3 pg(128, 3);
  proj_kernel<<<pg, 128>>>(q, k, v, Wq, bq, Wk, bk, Wv, bv);
  attn_split_kernel<<<S_SPLIT * BATCH * (SEQ / 64), 128, ATTN_SMEM>>>();
  combine_kernel<<<BATCH * (SEQ / 32), 256>>>(out, gr[0], gc[0], gr[1], gc[1],
                                              gr[2], gc[2]);
}